// round 13
// baseline (speedup 1.0000x reference)
#include <cuda_runtime.h>
#include <stdint.h>

#define WBLOCK 32                  // scan: 1 warp per block
#define TILE 512                   // elements per tile (one warp)
#define PASS 128                   // elements per pass (4 per lane)
#define NPASS 4
#define MAXTILES 8192
#define EB 128                     // epilogue threads per block
#define EPB (EB * 8)               // 1024 elements per epilogue block

#define GAMMA_F 0.99f
#define LAMBDA_F 0.95f
#define CLIP_EPS_F 0.2f
#define GL (GAMMA_F * LAMBDA_F)
#define GL4 (GL * GL * GL * GL)

// ---- device scratch ----
__device__ float  g_adv[1 << 22];
__device__ double g_psum[MAXTILES];
__device__ double g_psq[MAXTILES];
__device__ float  g_mean;
__device__ float  g_rinv;
__device__ int    g_boolByteLayout;

// ===== kernel 0: one-warp bool layout detection =====
__global__ void detect_kernel(const uint8_t* __restrict__ t1,
                              const uint8_t* __restrict__ t2, int n) {
    const int lane = threadIdx.x;
    int predv = 0;
    if (n >= 512) {
        uint4 x = __ldg((const uint4*)t1 + lane);
        uint4 y = __ldg((const uint4*)t2 + lane);
        predv = ((x.x | x.y | x.z | x.w | y.x | y.y | y.z | y.w) & 0xFFFFFF00u) != 0;
    } else {
        for (int i = lane; i < n; i += 32)
            if ((i & 3) && (t1[i] | t2[i])) predv = 1;
    }
    int r = __any_sync(0xFFFFFFFFu, predv);
    if (lane == 0) g_boolByteLayout = r;
}

// guarded scalar load of 4 (c,d) pairs (tail only)
__device__ __forceinline__ void load_cd4_guard(long long b, int n, int byteLayout,
                                               const float* __restrict__ rewards,
                                               const float* __restrict__ values,
                                               const float* __restrict__ next_values,
                                               const void* __restrict__ term_raw,
                                               const void* __restrict__ trun_raw,
                                               float* cc, float* dd) {
#pragma unroll
    for (int j = 0; j < 4; j++) {
        long long idx = b + j;
        if (idx < (long long)n) {
            bool b_te, b_tu;
            if (byteLayout) {
                b_te = ((const uint8_t*)term_raw)[idx] != 0;
                b_tu = ((const uint8_t*)trun_raw)[idx] != 0;
            } else {
                b_te = ((const int*)term_raw)[idx] != 0;
                b_tu = ((const int*)trun_raw)[idx] != 0;
            }
            float nt = b_te ? 0.f : 1.f;
            dd[j] = rewards[idx] + GAMMA_F * nt * next_values[idx] - values[idx];
            cc[j] = (b_te || b_tu) ? 0.f : GL;
        } else { cc[j] = 1.f; dd[j] = 0.f; }
    }
}

__device__ __forceinline__ void warp_suffix_scan1(float& iC, float& iD, int lane) {
#pragma unroll
    for (int off = 1; off < 32; off <<= 1) {
        float oc = __shfl_down_sync(0xFFFFFFFFu, iC, off);
        float od = __shfl_down_sync(0xFFFFFFFFu, iD, off);
        float nD = fmaf(iC, od, iD);
        float nC = iC * oc;
        if (lane + off < 32) { iC = nC; iD = nD; }
    }
}

// ===== kernel A: scan; float loads hoisted above layout branch =====
__global__ __launch_bounds__(WBLOCK)
void scan_kernel(const float* __restrict__ rewards,
                 const float* __restrict__ values,
                 const float* __restrict__ next_values,
                 const void* __restrict__ term_raw,
                 const void* __restrict__ trun_raw,
                 int n, int numTiles)
{
    const int lane = threadIdx.x;
    const int tile = blockIdx.x;

    float accSum = 0.f, accSq = 0.f;
    const long long tileStart = (long long)tile * TILE;
    const long long tileEnd   = tileStart + TILE;

    const bool fastHalo = (tileEnd + 64 <= (long long)n);

    if (tileEnd <= (long long)n && (fastHalo || tileEnd == (long long)n)) {
        // ---------- fast path ----------
        float ddp[16];           // r - v
        float4 NVf[NPASS];
        {
#pragma unroll
            for (int p = 0; p < NPASS; p++) {
                const long long b = tileStart + (long long)p * PASS + lane * 4;
                float4 rr = __ldg((const float4*)(rewards + b));
                float4 vv = __ldg((const float4*)(values + b));
                NVf[p]    = __ldg((const float4*)(next_values + b));
                ddp[p*4+0] = rr.x - vv.x;
                ddp[p*4+1] = rr.y - vv.y;
                ddp[p*4+2] = rr.z - vv.z;
                ddp[p*4+3] = rr.w - vv.w;
            }
        }
        float2 hR = make_float2(0.f, 0.f), hV = hR, hN = hR;
        const long long hb = tileEnd + lane * 2;
        if (fastHalo) {
            hR = __ldg((const float2*)(rewards + hb));
            hV = __ldg((const float2*)(values + hb));
            hN = __ldg((const float2*)(next_values + hb));
        }

        const int byteLayout = g_boolByteLayout;
        unsigned dmask = 0;
        int hte0 = 0, hte1 = 0, htu0 = 0, htu1 = 0;
        if (byteLayout) {
#pragma unroll
            for (int p = 0; p < NPASS; p++) {
                const long long b = tileStart + (long long)p * PASS + lane * 4;
                unsigned tm = *(const unsigned*)((const uint8_t*)term_raw + b);
                unsigned tr = *(const unsigned*)((const uint8_t*)trun_raw + b);
#pragma unroll
                for (int j = 0; j < 4; j++) {
                    int te = (int)((tm >> (8 * j)) & 0xFFu);
                    int tu = (int)((tr >> (8 * j)) & 0xFFu);
                    if (te) dmask |= 0x10000u << (p * 4 + j);
                    if (te | tu) dmask |= 1u << (p * 4 + j);
                }
            }
            if (fastHalo) {
                unsigned short tm = *(const unsigned short*)((const uint8_t*)term_raw + hb);
                unsigned short tr = *(const unsigned short*)((const uint8_t*)trun_raw + hb);
                hte0 = tm & 0xFF; hte1 = (tm >> 8) & 0xFF;
                htu0 = tr & 0xFF; htu1 = (tr >> 8) & 0xFF;
            }
        } else {
#pragma unroll
            for (int p = 0; p < NPASS; p++) {
                const long long b = tileStart + (long long)p * PASS + lane * 4;
                int4 a0 = __ldg((const int4*)((const int*)term_raw + b));
                int4 b0 = __ldg((const int4*)((const int*)trun_raw + b));
                int te[4] = {a0.x, a0.y, a0.z, a0.w};
                int tu[4] = {b0.x, b0.y, b0.z, b0.w};
#pragma unroll
                for (int j = 0; j < 4; j++) {
                    if (te[j]) dmask |= 0x10000u << (p * 4 + j);
                    if (te[j] | tu[j]) dmask |= 1u << (p * 4 + j);
                }
            }
            if (fastHalo) {
                int2 a0 = __ldg((const int2*)((const int*)term_raw + hb));
                int2 b0 = __ldg((const int2*)((const int*)trun_raw + hb));
                hte0 = a0.x; hte1 = a0.y; htu0 = b0.x; htu1 = b0.y;
            }
        }

        float dd[16];
        {
            float nv4[16];
#pragma unroll
            for (int p = 0; p < NPASS; p++) {
                nv4[p*4+0] = NVf[p].x; nv4[p*4+1] = NVf[p].y;
                nv4[p*4+2] = NVf[p].z; nv4[p*4+3] = NVf[p].w;
            }
#pragma unroll
            for (int k = 0; k < 16; k++) {
                float nt = (dmask & (0x10000u << k)) ? 0.f : GAMMA_F;
                dd[k] = fmaf(nt, nv4[k], ddp[k]);
            }
        }

        float iC[5], iD[5];
        {
            float hC = 1.f, hD = 0.f;
            if (fastHalo) {
                float nt0 = hte0 ? 0.f : 1.f, nt1 = hte1 ? 0.f : 1.f;
                float d0 = hR.x + GAMMA_F * nt0 * hN.x - hV.x;
                float d1 = hR.y + GAMMA_F * nt1 * hN.y - hV.y;
                float c0 = (hte0 | htu0) ? 0.f : GL;
                float c1 = (hte1 | htu1) ? 0.f : GL;
                hC = c0 * c1;
                hD = fmaf(c0, d1, d0);
            }
            iC[4] = hC; iD[4] = hD;
        }

#pragma unroll
        for (int p = 0; p < NPASS; p++) {
            const unsigned nib = (dmask >> (p * 4)) & 0xFu;
            float C = (nib == 0u) ? GL4 : 0.f;
            float D = 0.f;
#pragma unroll
            for (int j = 3; j >= 0; j--) {
                float cj = (nib & (1u << j)) ? 0.f : GL;
                D = fmaf(cj, D, dd[p * 4 + j]);
            }
            iC[p] = C; iD[p] = D;
        }

#pragma unroll
        for (int off = 1; off < 32; off <<= 1) {
            float oc[5], od[5];
#pragma unroll
            for (int q = 0; q < 5; q++) {
                oc[q] = __shfl_down_sync(0xFFFFFFFFu, iC[q], off);
                od[q] = __shfl_down_sync(0xFFFFFFFFu, iD[q], off);
            }
            const bool in = (lane + off) < 32;
#pragma unroll
            for (int q = 0; q < 5; q++) {
                float nD = fmaf(iC[q], od[q], iD[q]);
                float nC = iC[q] * oc[q];
                if (in) { iC[q] = nC; iD[q] = nD; }
            }
        }

        float eC[4], eD[4];
#pragma unroll
        for (int q = 0; q < NPASS; q++) {
            eC[q] = __shfl_down_sync(0xFFFFFFFFu, iC[q], 1);
            eD[q] = __shfl_down_sync(0xFFFFFFFFu, iD[q], 1);
            if (lane == 31) { eC[q] = 1.f; eD[q] = 0.f; }
        }

        float aggC[4], aggD[4];
#pragma unroll
        for (int q = 0; q < NPASS; q++) {
            aggC[q] = __shfl_sync(0xFFFFFFFFu, iC[q], 0);
            aggD[q] = __shfl_sync(0xFFFFFFFFu, iD[q], 0);
        }
        const float seedH = __shfl_sync(0xFFFFFFFFu, iD[4], 0);
        float seed[4];
        seed[3] = seedH;
        seed[2] = fmaf(aggC[3], seed[3], aggD[3]);
        seed[1] = fmaf(aggC[2], seed[2], aggD[2]);
        seed[0] = fmaf(aggC[1], seed[1], aggD[1]);

#pragma unroll
        for (int p = 0; p < NPASS; p++) {
            const unsigned nib = (dmask >> (p * 4)) & 0xFu;
            float x = fmaf(eC[p], seed[p], eD[p]);
            float c3 = (nib & 8u) ? 0.f : GL;
            float c2 = (nib & 4u) ? 0.f : GL;
            float c1 = (nib & 2u) ? 0.f : GL;
            float c0 = (nib & 1u) ? 0.f : GL;
            float o0, o1, o2, o3;
            x = fmaf(c3, x, dd[p * 4 + 3]); o3 = x;
            x = fmaf(c2, x, dd[p * 4 + 2]); o2 = x;
            x = fmaf(c1, x, dd[p * 4 + 1]); o1 = x;
            x = fmaf(c0, x, dd[p * 4 + 0]); o0 = x;
            accSum += o0 + o1 + o2 + o3;
            accSq = fmaf(o0, o0, accSq); accSq = fmaf(o1, o1, accSq);
            accSq = fmaf(o2, o2, accSq); accSq = fmaf(o3, o3, accSq);
            *(float4*)(g_adv + tileStart + (long long)p * PASS + lane * 4) =
                make_float4(o0, o1, o2, o3);
        }
    } else {
        // ---------- tail / near-tail tiles (rare): guarded sequential ----------
        const int byteLayout = g_boolByteLayout;
        float seed = 0.f;
        if (tileEnd < (long long)n) {
            float hcc[2], hdd[2];
            const long long hb2 = tileEnd + lane * 2;
#pragma unroll
            for (int j = 0; j < 2; j++) {
                long long idx = hb2 + j;
                hcc[j] = 1.f; hdd[j] = 0.f;
                if (idx < (long long)n) {
                    bool b_te, b_tu;
                    if (byteLayout) {
                        b_te = ((const uint8_t*)term_raw)[idx] != 0;
                        b_tu = ((const uint8_t*)trun_raw)[idx] != 0;
                    } else {
                        b_te = ((const int*)term_raw)[idx] != 0;
                        b_tu = ((const int*)trun_raw)[idx] != 0;
                    }
                    float nt = b_te ? 0.f : 1.f;
                    hdd[j] = rewards[idx] + GAMMA_F * nt * next_values[idx] - values[idx];
                    hcc[j] = (b_te || b_tu) ? 0.f : GL;
                }
            }
            float hC = hcc[0] * hcc[1];
            float hD = fmaf(hcc[0], hdd[1], hdd[0]);
            warp_suffix_scan1(hC, hD, lane);
            seed = __shfl_sync(0xFFFFFFFFu, hD, 0);
        }
        for (int p = NPASS - 1; p >= 0; p--) {
            float cc[4], ddl[4];
            const long long b = tileStart + (long long)p * PASS + lane * 4;
            load_cd4_guard(b, n, byteLayout,
                           rewards, values, next_values, term_raw, trun_raw, cc, ddl);
            float C = 1.f, D = 0.f;
#pragma unroll
            for (int j = 3; j >= 0; j--) { D = fmaf(cc[j], D, ddl[j]); C *= cc[j]; }
            float iCx = C, iDx = D;
            warp_suffix_scan1(iCx, iDx, lane);
            float eCx = __shfl_down_sync(0xFFFFFFFFu, iCx, 1);
            float eDx = __shfl_down_sync(0xFFFFFFFFu, iDx, 1);
            if (lane == 31) { eCx = 1.f; eDx = 0.f; }
            float x = fmaf(eCx, seed, eDx);
#pragma unroll
            for (int j = 3; j >= 0; j--) {
                x = fmaf(cc[j], x, ddl[j]);
                long long idx = b + j;
                if (idx < (long long)n) {
                    g_adv[idx] = x;
                    accSum += x; accSq = fmaf(x, x, accSq);
                }
            }
            float ns = fmaf(iCx, seed, iDx);
            seed = __shfl_sync(0xFFFFFFFFu, ns, 0);
        }
    }

    // ---- warp(=block) partial sums ----
    double ds = (double)accSum, dq = (double)accSq;
#pragma unroll
    for (int o = 16; o > 0; o >>= 1) {
        ds += __shfl_down_sync(0xFFFFFFFFu, ds, o);
        dq += __shfl_down_sync(0xFFFFFFFFu, dq, o);
    }
    if (lane == 0) { g_psum[tile] = ds; g_psq[tile] = dq; }
}

// ===== kernel B: stats (1024 threads) =====
__global__ void stats_kernel(int numTiles, int n) {
    __shared__ double s_wsum[32];
    __shared__ double s_wsq[32];
    const int t = threadIdx.x;
    const int lane = t & 31, wrp = t >> 5;
    double ds = 0.0, dq = 0.0;
    for (int i = t; i < numTiles; i += 1024) { ds += g_psum[i]; dq += g_psq[i]; }
#pragma unroll
    for (int o = 16; o > 0; o >>= 1) {
        ds += __shfl_down_sync(0xFFFFFFFFu, ds, o);
        dq += __shfl_down_sync(0xFFFFFFFFu, dq, o);
    }
    if (lane == 0) { s_wsum[wrp] = ds; s_wsq[wrp] = dq; }
    __syncthreads();
    if (t == 0) {
        double ts = 0.0, tq = 0.0;
#pragma unroll
        for (int w = 0; w < 32; w++) { ts += s_wsum[w]; tq += s_wsq[w]; }
        double mean = ts / (double)n;
        double var = (tq - ts * ts / (double)n) / (double)(n - 1);
        if (var < 0.0) var = 0.0;
        g_mean = (float)mean;
        g_rinv = (float)(1.0 / (sqrt(var) + 1e-9));
    }
}

__device__ __forceinline__ void ppo_row(float a, float v, float lp, float olp,
                                        float mean, float rinv, float* o) {
    float an = (a - mean) * rinv;
    float lr = a + v;
    float ratio = __expf(lp - olp);
    float cl = fminf(fmaxf(ratio, 1.f - CLIP_EPS_F), 1.f + CLIP_EPS_F);
    float loss = -fminf(ratio * an, cl * an);
    o[0] = an; o[1] = lr; o[2] = loss;
}

// ===== kernel C: epilogue, 2 independent float4 groups per thread =====
__global__ __launch_bounds__(EB)
void output_kernel(const float* __restrict__ values,
                   const float* __restrict__ log_probs,
                   const float* __restrict__ old_log_probs,
                   float* __restrict__ out, int n)
{
    __shared__ float4 s4[6 * EB];       // 768 float4 = block's 3072 out floats
    const float mean = g_mean, rinv = g_rinv;
    const int t = threadIdx.x;
    const long long blockBase = (long long)blockIdx.x * EPB;

    if (blockBase + EPB <= (long long)n) {
        // two independent chains, interleaved loads for MLP
        const long long b0 = blockBase + t * 4;
        const long long b1 = blockBase + EB * 4 + t * 4;
        float4 a0   = *(const float4*)(g_adv + b0);
        float4 a1   = *(const float4*)(g_adv + b1);
        float4 v0   = __ldg((const float4*)(values + b0));
        float4 v1   = __ldg((const float4*)(values + b1));
        float4 lp0  = __ldcs((const float4*)(log_probs + b0));
        float4 lp1  = __ldcs((const float4*)(log_probs + b1));
        float4 op0  = __ldcs((const float4*)(old_log_probs + b0));
        float4 op1  = __ldcs((const float4*)(old_log_probs + b1));

        float o[12];
        ppo_row(a0.x, v0.x, lp0.x, op0.x, mean, rinv, o + 0);
        ppo_row(a0.y, v0.y, lp0.y, op0.y, mean, rinv, o + 3);
        ppo_row(a0.z, v0.z, lp0.z, op0.z, mean, rinv, o + 6);
        ppo_row(a0.w, v0.w, lp0.w, op0.w, mean, rinv, o + 9);
        s4[3 * t + 0] = make_float4(o[0], o[1], o[2],  o[3]);
        s4[3 * t + 1] = make_float4(o[4], o[5], o[6],  o[7]);
        s4[3 * t + 2] = make_float4(o[8], o[9], o[10], o[11]);

        ppo_row(a1.x, v1.x, lp1.x, op1.x, mean, rinv, o + 0);
        ppo_row(a1.y, v1.y, lp1.y, op1.y, mean, rinv, o + 3);
        ppo_row(a1.z, v1.z, lp1.z, op1.z, mean, rinv, o + 6);
        ppo_row(a1.w, v1.w, lp1.w, op1.w, mean, rinv, o + 9);
        s4[3 * EB + 3 * t + 0] = make_float4(o[0], o[1], o[2],  o[3]);
        s4[3 * EB + 3 * t + 1] = make_float4(o[4], o[5], o[6],  o[7]);
        s4[3 * EB + 3 * t + 2] = make_float4(o[8], o[9], o[10], o[11]);

        __syncthreads();
        float4* dst = (float4*)(out + blockBase * 3);
#pragma unroll
        for (int k = 0; k < 6; k++)
            __stcs(dst + t + k * EB, s4[t + k * EB]);
    } else {
        for (long long i = blockBase + t * 8; i < blockBase + t * 8 + 8 && i < (long long)n; i++) {
            float o[3];
            ppo_row(g_adv[i], values[i], log_probs[i], old_log_probs[i], mean, rinv, o);
            out[i * 3 + 0] = o[0];
            out[i * 3 + 1] = o[1];
            out[i * 3 + 2] = o[2];
        }
    }
}

extern "C" void kernel_launch(void* const* d_in, const int* in_sizes, int n_in,
                              void* d_out, int out_size) {
    const float* rewards       = (const float*)d_in[0];
    const float* values        = (const float*)d_in[1];
    const float* next_values   = (const float*)d_in[2];
    const float* log_probs     = (const float*)d_in[3];
    const float* old_log_probs = (const float*)d_in[4];
    const void*  terminated    = d_in[5];
    const void*  truncated     = d_in[6];
    float* out = (float*)d_out;

    int n = in_sizes[0];
    int numTiles = (n + TILE - 1) / TILE;              // 4096 for N=2M
    if (numTiles > MAXTILES) numTiles = MAXTILES;
    int gridC = (int)(((long long)n + EPB - 1) / EPB); // 2048

    detect_kernel<<<1, 32>>>((const uint8_t*)terminated, (const uint8_t*)truncated, n);
    scan_kernel<<<numTiles, WBLOCK>>>(rewards, values, next_values,
                                      terminated, truncated, n, numTiles);
    stats_kernel<<<1, 1024>>>(numTiles, n);
    output_kernel<<<gridC, EB>>>(values, log_probs, old_log_probs, out, n);
}

// round 14
// speedup vs baseline: 1.0104x; 1.0104x over previous
#include <cuda_runtime.h>
#include <stdint.h>

#define WBLOCK 32                  // scan: 1 warp per block
#define TILE 512                   // elements per tile (one warp)
#define PASS 128                   // elements per pass (4 per lane)
#define NPASS 4
#define NBUCKET 128
#define OBLOCK 256                 // epilogue block

#define GAMMA_F 0.99f
#define LAMBDA_F 0.95f
#define CLIP_EPS_F 0.2f
#define GL (GAMMA_F * LAMBDA_F)
#define GL4 (GL * GL * GL * GL)

// ---- device scratch ----
__device__ float  g_adv[1 << 22];
__device__ double g_psumA[NBUCKET];
__device__ double g_psqA[NBUCKET];
__device__ int    g_boolByteLayout;

// ===== kernel 0: init buckets + bool layout detection =====
__global__ void detect_init_kernel(const uint8_t* __restrict__ t1,
                                   const uint8_t* __restrict__ t2, int n) {
    const int t = threadIdx.x;
    if (t < NBUCKET) { g_psumA[t] = 0.0; g_psqA[t] = 0.0; }
    if (t < 32) {
        const int lane = t;
        int predv = 0;
        if (n >= 512) {
            uint4 x = __ldg((const uint4*)t1 + lane);
            uint4 y = __ldg((const uint4*)t2 + lane);
            predv = ((x.x | x.y | x.z | x.w | y.x | y.y | y.z | y.w) & 0xFFFFFF00u) != 0;
        } else {
            for (int i = lane; i < n; i += 32)
                if ((i & 3) && (t1[i] | t2[i])) predv = 1;
        }
        int r = __any_sync(0xFFFFFFFFu, predv);
        if (lane == 0) g_boolByteLayout = r;
    }
}

// guarded scalar load of 4 (c,d) pairs (tail only)
__device__ __forceinline__ void load_cd4_guard(long long b, int n, int byteLayout,
                                               const float* __restrict__ rewards,
                                               const float* __restrict__ values,
                                               const float* __restrict__ next_values,
                                               const void* __restrict__ term_raw,
                                               const void* __restrict__ trun_raw,
                                               float* cc, float* dd) {
#pragma unroll
    for (int j = 0; j < 4; j++) {
        long long idx = b + j;
        if (idx < (long long)n) {
            bool b_te, b_tu;
            if (byteLayout) {
                b_te = ((const uint8_t*)term_raw)[idx] != 0;
                b_tu = ((const uint8_t*)trun_raw)[idx] != 0;
            } else {
                b_te = ((const int*)term_raw)[idx] != 0;
                b_tu = ((const int*)trun_raw)[idx] != 0;
            }
            float nt = b_te ? 0.f : 1.f;
            dd[j] = rewards[idx] + GAMMA_F * nt * next_values[idx] - values[idx];
            cc[j] = (b_te || b_tu) ? 0.f : GL;
        } else { cc[j] = 1.f; dd[j] = 0.f; }
    }
}

__device__ __forceinline__ void warp_suffix_scan1(float& iC, float& iD, int lane) {
#pragma unroll
    for (int off = 1; off < 32; off <<= 1) {
        float oc = __shfl_down_sync(0xFFFFFFFFu, iC, off);
        float od = __shfl_down_sync(0xFFFFFFFFu, iD, off);
        float nD = fmaf(iC, od, iD);
        float nC = iC * oc;
        if (lane + off < 32) { iC = nC; iD = nD; }
    }
}

// ===== kernel A: scan (round-12 form; partials via spread atomics) =====
__global__ __launch_bounds__(WBLOCK)
void scan_kernel(const float* __restrict__ rewards,
                 const float* __restrict__ values,
                 const float* __restrict__ next_values,
                 const void* __restrict__ term_raw,
                 const void* __restrict__ trun_raw,
                 int n, int numTiles)
{
    const int lane = threadIdx.x;
    const int tile = blockIdx.x;

    float accSum = 0.f, accSq = 0.f;
    const long long tileStart = (long long)tile * TILE;
    const long long tileEnd   = tileStart + TILE;

    const bool fastHalo = (tileEnd + 64 <= (long long)n);

    if (tileEnd <= (long long)n && (fastHalo || tileEnd == (long long)n)) {
        // ---------- fast path ----------
        float ddp[16];           // r - v
        float4 NVf[NPASS];
#pragma unroll
        for (int p = 0; p < NPASS; p++) {
            const long long b = tileStart + (long long)p * PASS + lane * 4;
            float4 rr = __ldg((const float4*)(rewards + b));
            float4 vv = __ldg((const float4*)(values + b));
            NVf[p]    = __ldg((const float4*)(next_values + b));
            ddp[p*4+0] = rr.x - vv.x;
            ddp[p*4+1] = rr.y - vv.y;
            ddp[p*4+2] = rr.z - vv.z;
            ddp[p*4+3] = rr.w - vv.w;
        }
        float2 hR = make_float2(0.f, 0.f), hV = hR, hN = hR;
        const long long hb = tileEnd + lane * 2;
        if (fastHalo) {
            hR = __ldg((const float2*)(rewards + hb));
            hV = __ldg((const float2*)(values + hb));
            hN = __ldg((const float2*)(next_values + hb));
        }

        const int byteLayout = g_boolByteLayout;
        unsigned dmask = 0;
        int hte0 = 0, hte1 = 0, htu0 = 0, htu1 = 0;
        if (byteLayout) {
#pragma unroll
            for (int p = 0; p < NPASS; p++) {
                const long long b = tileStart + (long long)p * PASS + lane * 4;
                unsigned tm = *(const unsigned*)((const uint8_t*)term_raw + b);
                unsigned tr = *(const unsigned*)((const uint8_t*)trun_raw + b);
#pragma unroll
                for (int j = 0; j < 4; j++) {
                    int te = (int)((tm >> (8 * j)) & 0xFFu);
                    int tu = (int)((tr >> (8 * j)) & 0xFFu);
                    if (te) dmask |= 0x10000u << (p * 4 + j);
                    if (te | tu) dmask |= 1u << (p * 4 + j);
                }
            }
            if (fastHalo) {
                unsigned short tm = *(const unsigned short*)((const uint8_t*)term_raw + hb);
                unsigned short tr = *(const unsigned short*)((const uint8_t*)trun_raw + hb);
                hte0 = tm & 0xFF; hte1 = (tm >> 8) & 0xFF;
                htu0 = tr & 0xFF; htu1 = (tr >> 8) & 0xFF;
            }
        } else {
#pragma unroll
            for (int p = 0; p < NPASS; p++) {
                const long long b = tileStart + (long long)p * PASS + lane * 4;
                int4 a0 = __ldg((const int4*)((const int*)term_raw + b));
                int4 b0 = __ldg((const int4*)((const int*)trun_raw + b));
                int te[4] = {a0.x, a0.y, a0.z, a0.w};
                int tu[4] = {b0.x, b0.y, b0.z, b0.w};
#pragma unroll
                for (int j = 0; j < 4; j++) {
                    if (te[j]) dmask |= 0x10000u << (p * 4 + j);
                    if (te[j] | tu[j]) dmask |= 1u << (p * 4 + j);
                }
            }
            if (fastHalo) {
                int2 a0 = __ldg((const int2*)((const int*)term_raw + hb));
                int2 b0 = __ldg((const int2*)((const int*)trun_raw + hb));
                hte0 = a0.x; hte1 = a0.y; htu0 = b0.x; htu1 = b0.y;
            }
        }

        float dd[16];
        {
            float nv4[16];
#pragma unroll
            for (int p = 0; p < NPASS; p++) {
                nv4[p*4+0] = NVf[p].x; nv4[p*4+1] = NVf[p].y;
                nv4[p*4+2] = NVf[p].z; nv4[p*4+3] = NVf[p].w;
            }
#pragma unroll
            for (int k = 0; k < 16; k++) {
                float nt = (dmask & (0x10000u << k)) ? 0.f : GAMMA_F;
                dd[k] = fmaf(nt, nv4[k], ddp[k]);
            }
        }

        float iC[5], iD[5];
        {
            float hC = 1.f, hD = 0.f;
            if (fastHalo) {
                float nt0 = hte0 ? 0.f : 1.f, nt1 = hte1 ? 0.f : 1.f;
                float d0 = hR.x + GAMMA_F * nt0 * hN.x - hV.x;
                float d1 = hR.y + GAMMA_F * nt1 * hN.y - hV.y;
                float c0 = (hte0 | htu0) ? 0.f : GL;
                float c1 = (hte1 | htu1) ? 0.f : GL;
                hC = c0 * c1;
                hD = fmaf(c0, d1, d0);
            }
            iC[4] = hC; iD[4] = hD;
        }

#pragma unroll
        for (int p = 0; p < NPASS; p++) {
            const unsigned nib = (dmask >> (p * 4)) & 0xFu;
            float C = (nib == 0u) ? GL4 : 0.f;
            float D = 0.f;
#pragma unroll
            for (int j = 3; j >= 0; j--) {
                float cj = (nib & (1u << j)) ? 0.f : GL;
                D = fmaf(cj, D, dd[p * 4 + j]);
            }
            iC[p] = C; iD[p] = D;
        }

#pragma unroll
        for (int off = 1; off < 32; off <<= 1) {
            float oc[5], od[5];
#pragma unroll
            for (int q = 0; q < 5; q++) {
                oc[q] = __shfl_down_sync(0xFFFFFFFFu, iC[q], off);
                od[q] = __shfl_down_sync(0xFFFFFFFFu, iD[q], off);
            }
            const bool in = (lane + off) < 32;
#pragma unroll
            for (int q = 0; q < 5; q++) {
                float nD = fmaf(iC[q], od[q], iD[q]);
                float nC = iC[q] * oc[q];
                if (in) { iC[q] = nC; iD[q] = nD; }
            }
        }

        float eC[4], eD[4];
#pragma unroll
        for (int q = 0; q < NPASS; q++) {
            eC[q] = __shfl_down_sync(0xFFFFFFFFu, iC[q], 1);
            eD[q] = __shfl_down_sync(0xFFFFFFFFu, iD[q], 1);
            if (lane == 31) { eC[q] = 1.f; eD[q] = 0.f; }
        }

        float aggC[4], aggD[4];
#pragma unroll
        for (int q = 0; q < NPASS; q++) {
            aggC[q] = __shfl_sync(0xFFFFFFFFu, iC[q], 0);
            aggD[q] = __shfl_sync(0xFFFFFFFFu, iD[q], 0);
        }
        const float seedH = __shfl_sync(0xFFFFFFFFu, iD[4], 0);
        float seed[4];
        seed[3] = seedH;
        seed[2] = fmaf(aggC[3], seed[3], aggD[3]);
        seed[1] = fmaf(aggC[2], seed[2], aggD[2]);
        seed[0] = fmaf(aggC[1], seed[1], aggD[1]);

#pragma unroll
        for (int p = 0; p < NPASS; p++) {
            const unsigned nib = (dmask >> (p * 4)) & 0xFu;
            float x = fmaf(eC[p], seed[p], eD[p]);
            float c3 = (nib & 8u) ? 0.f : GL;
            float c2 = (nib & 4u) ? 0.f : GL;
            float c1 = (nib & 2u) ? 0.f : GL;
            float c0 = (nib & 1u) ? 0.f : GL;
            float o0, o1, o2, o3;
            x = fmaf(c3, x, dd[p * 4 + 3]); o3 = x;
            x = fmaf(c2, x, dd[p * 4 + 2]); o2 = x;
            x = fmaf(c1, x, dd[p * 4 + 1]); o1 = x;
            x = fmaf(c0, x, dd[p * 4 + 0]); o0 = x;
            accSum += o0 + o1 + o2 + o3;
            accSq = fmaf(o0, o0, accSq); accSq = fmaf(o1, o1, accSq);
            accSq = fmaf(o2, o2, accSq); accSq = fmaf(o3, o3, accSq);
            *(float4*)(g_adv + tileStart + (long long)p * PASS + lane * 4) =
                make_float4(o0, o1, o2, o3);
        }
    } else {
        // ---------- tail / near-tail tiles (rare) ----------
        const int byteLayout = g_boolByteLayout;
        float seed = 0.f;
        if (tileEnd < (long long)n) {
            float hcc[2], hdd[2];
            const long long hb2 = tileEnd + lane * 2;
#pragma unroll
            for (int j = 0; j < 2; j++) {
                long long idx = hb2 + j;
                hcc[j] = 1.f; hdd[j] = 0.f;
                if (idx < (long long)n) {
                    bool b_te, b_tu;
                    if (byteLayout) {
                        b_te = ((const uint8_t*)term_raw)[idx] != 0;
                        b_tu = ((const uint8_t*)trun_raw)[idx] != 0;
                    } else {
                        b_te = ((const int*)term_raw)[idx] != 0;
                        b_tu = ((const int*)trun_raw)[idx] != 0;
                    }
                    float nt = b_te ? 0.f : 1.f;
                    hdd[j] = rewards[idx] + GAMMA_F * nt * next_values[idx] - values[idx];
                    hcc[j] = (b_te || b_tu) ? 0.f : GL;
                }
            }
            float hC = hcc[0] * hcc[1];
            float hD = fmaf(hcc[0], hdd[1], hdd[0]);
            warp_suffix_scan1(hC, hD, lane);
            seed = __shfl_sync(0xFFFFFFFFu, hD, 0);
        }
        for (int p = NPASS - 1; p >= 0; p--) {
            float cc[4], ddl[4];
            const long long b = tileStart + (long long)p * PASS + lane * 4;
            load_cd4_guard(b, n, byteLayout,
                           rewards, values, next_values, term_raw, trun_raw, cc, ddl);
            float C = 1.f, D = 0.f;
#pragma unroll
            for (int j = 3; j >= 0; j--) { D = fmaf(cc[j], D, ddl[j]); C *= cc[j]; }
            float iCx = C, iDx = D;
            warp_suffix_scan1(iCx, iDx, lane);
            float eCx = __shfl_down_sync(0xFFFFFFFFu, iCx, 1);
            float eDx = __shfl_down_sync(0xFFFFFFFFu, iDx, 1);
            if (lane == 31) { eCx = 1.f; eDx = 0.f; }
            float x = fmaf(eCx, seed, eDx);
#pragma unroll
            for (int j = 3; j >= 0; j--) {
                x = fmaf(cc[j], x, ddl[j]);
                long long idx = b + j;
                if (idx < (long long)n) {
                    g_adv[idx] = x;
                    accSum += x; accSq = fmaf(x, x, accSq);
                }
            }
            float ns = fmaf(iCx, seed, iDx);
            seed = __shfl_sync(0xFFFFFFFFu, ns, 0);
        }
    }

    // ---- warp partial sums -> spread atomics (32 per bucket) ----
    double ds = (double)accSum, dq = (double)accSq;
#pragma unroll
    for (int o = 16; o > 0; o >>= 1) {
        ds += __shfl_down_sync(0xFFFFFFFFu, ds, o);
        dq += __shfl_down_sync(0xFFFFFFFFu, dq, o);
    }
    if (lane == 0) {
        atomicAdd(&g_psumA[tile & (NBUCKET - 1)], ds);
        atomicAdd(&g_psqA[tile & (NBUCKET - 1)], dq);
    }
}

__device__ __forceinline__ void ppo_row(float a, float v, float lp, float olp,
                                        float mean, float rinv, float* o) {
    float an = (a - mean) * rinv;
    float lr = a + v;
    float ratio = __expf(lp - olp);
    float cl = fminf(fmaxf(ratio, 1.f - CLIP_EPS_F), 1.f + CLIP_EPS_F);
    float loss = -fminf(ratio * an, cl * an);
    o[0] = an; o[1] = lr; o[2] = loss;
}

// ===== kernel C: epilogue (round-12 form + local stats reduce) =====
__global__ __launch_bounds__(OBLOCK)
void output_kernel(const float* __restrict__ values,
                   const float* __restrict__ log_probs,
                   const float* __restrict__ old_log_probs,
                   float* __restrict__ out, int n)
{
    __shared__ float4 s4[3 * OBLOCK];
    __shared__ double sred[OBLOCK / 32];
    __shared__ float s_mr[2];

    const int t = threadIdx.x;
    const int lane = t & 31, wrp = t >> 5;
    const long long blockBase = (long long)blockIdx.x * (OBLOCK * 4);
    const long long b4 = blockBase + t * 4;
    const bool full = (blockBase + OBLOCK * 4 <= (long long)n);

    // issue main loads first (independent of stats)
    float4 a = make_float4(0,0,0,0), v = a, lp = a, olp = a;
    if (full) {
        a   = *(const float4*)(g_adv + b4);
        v   = __ldg((const float4*)(values + b4));
        lp  = __ldg((const float4*)(log_probs + b4));
        olp = __ldg((const float4*)(old_log_probs + b4));
    }

    // local stats reduce: warps 0-3 sum psumA, warps 4-7 sum psqA
    {
        double dv = (t < NBUCKET) ? g_psumA[t] : g_psqA[t - NBUCKET];
#pragma unroll
        for (int o = 16; o > 0; o >>= 1)
            dv += __shfl_down_sync(0xFFFFFFFFu, dv, o);
        if (lane == 0) sred[wrp] = dv;
    }
    __syncthreads();
    if (t == 0) {
        double ts = sred[0] + sred[1] + sred[2] + sred[3];
        double tq = sred[4] + sred[5] + sred[6] + sred[7];
        double mean = ts / (double)n;
        double var = (tq - ts * ts / (double)n) / (double)(n - 1);
        if (var < 0.0) var = 0.0;
        s_mr[0] = (float)mean;
        s_mr[1] = (float)(1.0 / (sqrt(var) + 1e-9));
    }
    __syncthreads();
    const float mean = s_mr[0], rinv = s_mr[1];

    if (full) {
        float o[12];
        ppo_row(a.x, v.x, lp.x, olp.x, mean, rinv, o + 0);
        ppo_row(a.y, v.y, lp.y, olp.y, mean, rinv, o + 3);
        ppo_row(a.z, v.z, lp.z, olp.z, mean, rinv, o + 6);
        ppo_row(a.w, v.w, lp.w, olp.w, mean, rinv, o + 9);
        s4[3 * t + 0] = make_float4(o[0], o[1], o[2],  o[3]);
        s4[3 * t + 1] = make_float4(o[4], o[5], o[6],  o[7]);
        s4[3 * t + 2] = make_float4(o[8], o[9], o[10], o[11]);
        __syncthreads();
        float4* dst = (float4*)(out + blockBase * 3);
        __stcs(dst + t,              s4[t]);
        __stcs(dst + t + OBLOCK,     s4[t + OBLOCK]);
        __stcs(dst + t + 2 * OBLOCK, s4[t + 2 * OBLOCK]);
    } else {
        for (long long i = b4; i < b4 + 4 && i < (long long)n; i++) {
            float o[3];
            ppo_row(g_adv[i], values[i], log_probs[i], old_log_probs[i], mean, rinv, o);
            out[i * 3 + 0] = o[0];
            out[i * 3 + 1] = o[1];
            out[i * 3 + 2] = o[2];
        }
    }
}

extern "C" void kernel_launch(void* const* d_in, const int* in_sizes, int n_in,
                              void* d_out, int out_size) {
    const float* rewards       = (const float*)d_in[0];
    const float* values        = (const float*)d_in[1];
    const float* next_values   = (const float*)d_in[2];
    const float* log_probs     = (const float*)d_in[3];
    const float* old_log_probs = (const float*)d_in[4];
    const void*  terminated    = d_in[5];
    const void*  truncated     = d_in[6];
    float* out = (float*)d_out;

    int n = in_sizes[0];
    int numTiles = (n + TILE - 1) / TILE;              // 4096 for N=2M
    int gridC = (int)(((long long)n + OBLOCK * 4 - 1) / (OBLOCK * 4));   // 2048

    detect_init_kernel<<<1, 256>>>((const uint8_t*)terminated, (const uint8_t*)truncated, n);
    scan_kernel<<<numTiles, WBLOCK>>>(rewards, values, next_values,
                                      terminated, truncated, n, numTiles);
    output_kernel<<<gridC, OBLOCK>>>(values, log_probs, old_log_probs, out, n);
}

// round 15
// speedup vs baseline: 1.2846x; 1.2714x over previous
#include <cuda_runtime.h>
#include <stdint.h>

#define WBLOCK 32                  // scan: 1 warp per block
#define TILE 512                   // elements per tile (one warp)
#define PASS 128                   // elements per pass (4 per lane)
#define NPASS 4
#define NBUCKET 128
#define OBLOCK 256                 // epilogue block

#define GAMMA_F 0.99f
#define LAMBDA_F 0.95f
#define CLIP_EPS_F 0.2f
#define GL (GAMMA_F * LAMBDA_F)
#define GL4 (GL * GL * GL * GL)

// ---- device scratch ----
__device__ float  g_adv[1 << 22];
__device__ double g_psumA[NBUCKET];
__device__ double g_psqA[NBUCKET];
__device__ float  g_mean;
__device__ float  g_rinv;
__device__ int    g_boolByteLayout;
__device__ unsigned g_scanDone;

// ===== kernel 0: reset buckets/counter + bool layout detection =====
__global__ void detect_init_kernel(const uint8_t* __restrict__ t1,
                                   const uint8_t* __restrict__ t2, int n) {
    const int t = threadIdx.x;
    if (t < NBUCKET) { g_psumA[t] = 0.0; g_psqA[t] = 0.0; }
    if (t == 255) g_scanDone = 0;
    if (t < 32) {
        const int lane = t;
        int predv = 0;
        if (n >= 512) {
            uint4 x = __ldg((const uint4*)t1 + lane);
            uint4 y = __ldg((const uint4*)t2 + lane);
            predv = ((x.x | x.y | x.z | x.w | y.x | y.y | y.z | y.w) & 0xFFFFFF00u) != 0;
        } else {
            for (int i = lane; i < n; i += 32)
                if ((i & 3) && (t1[i] | t2[i])) predv = 1;
        }
        int r = __any_sync(0xFFFFFFFFu, predv);
        if (lane == 0) g_boolByteLayout = r;
    }
}

// guarded scalar load of 4 (c,d) pairs (tail only)
__device__ __forceinline__ void load_cd4_guard(long long b, int n, int byteLayout,
                                               const float* __restrict__ rewards,
                                               const float* __restrict__ values,
                                               const float* __restrict__ next_values,
                                               const void* __restrict__ term_raw,
                                               const void* __restrict__ trun_raw,
                                               float* cc, float* dd) {
#pragma unroll
    for (int j = 0; j < 4; j++) {
        long long idx = b + j;
        if (idx < (long long)n) {
            bool b_te, b_tu;
            if (byteLayout) {
                b_te = ((const uint8_t*)term_raw)[idx] != 0;
                b_tu = ((const uint8_t*)trun_raw)[idx] != 0;
            } else {
                b_te = ((const int*)term_raw)[idx] != 0;
                b_tu = ((const int*)trun_raw)[idx] != 0;
            }
            float nt = b_te ? 0.f : 1.f;
            dd[j] = rewards[idx] + GAMMA_F * nt * next_values[idx] - values[idx];
            cc[j] = (b_te || b_tu) ? 0.f : GL;
        } else { cc[j] = 1.f; dd[j] = 0.f; }
    }
}

__device__ __forceinline__ void warp_suffix_scan1(float& iC, float& iD, int lane) {
#pragma unroll
    for (int off = 1; off < 32; off <<= 1) {
        float oc = __shfl_down_sync(0xFFFFFFFFu, iC, off);
        float od = __shfl_down_sync(0xFFFFFFFFu, iD, off);
        float nD = fmaf(iC, od, iD);
        float nC = iC * oc;
        if (lane + off < 32) { iC = nC; iD = nD; }
    }
}

// ===== kernel A: scan (round-12 form) + last-block stats fold =====
__global__ __launch_bounds__(WBLOCK)
void scan_kernel(const float* __restrict__ rewards,
                 const float* __restrict__ values,
                 const float* __restrict__ next_values,
                 const void* __restrict__ term_raw,
                 const void* __restrict__ trun_raw,
                 int n, int numTiles)
{
    const int lane = threadIdx.x;
    const int tile = blockIdx.x;

    float accSum = 0.f, accSq = 0.f;
    const long long tileStart = (long long)tile * TILE;
    const long long tileEnd   = tileStart + TILE;

    const bool fastHalo = (tileEnd + 64 <= (long long)n);

    if (tileEnd <= (long long)n && (fastHalo || tileEnd == (long long)n)) {
        // ---------- fast path ----------
        float ddp[16];           // r - v
        float4 NVf[NPASS];
#pragma unroll
        for (int p = 0; p < NPASS; p++) {
            const long long b = tileStart + (long long)p * PASS + lane * 4;
            float4 rr = __ldg((const float4*)(rewards + b));
            float4 vv = __ldg((const float4*)(values + b));
            NVf[p]    = __ldg((const float4*)(next_values + b));
            ddp[p*4+0] = rr.x - vv.x;
            ddp[p*4+1] = rr.y - vv.y;
            ddp[p*4+2] = rr.z - vv.z;
            ddp[p*4+3] = rr.w - vv.w;
        }
        float2 hR = make_float2(0.f, 0.f), hV = hR, hN = hR;
        const long long hb = tileEnd + lane * 2;
        if (fastHalo) {
            hR = __ldg((const float2*)(rewards + hb));
            hV = __ldg((const float2*)(values + hb));
            hN = __ldg((const float2*)(next_values + hb));
        }

        const int byteLayout = g_boolByteLayout;
        unsigned dmask = 0;
        int hte0 = 0, hte1 = 0, htu0 = 0, htu1 = 0;
        if (byteLayout) {
#pragma unroll
            for (int p = 0; p < NPASS; p++) {
                const long long b = tileStart + (long long)p * PASS + lane * 4;
                unsigned tm = *(const unsigned*)((const uint8_t*)term_raw + b);
                unsigned tr = *(const unsigned*)((const uint8_t*)trun_raw + b);
#pragma unroll
                for (int j = 0; j < 4; j++) {
                    int te = (int)((tm >> (8 * j)) & 0xFFu);
                    int tu = (int)((tr >> (8 * j)) & 0xFFu);
                    if (te) dmask |= 0x10000u << (p * 4 + j);
                    if (te | tu) dmask |= 1u << (p * 4 + j);
                }
            }
            if (fastHalo) {
                unsigned short tm = *(const unsigned short*)((const uint8_t*)term_raw + hb);
                unsigned short tr = *(const unsigned short*)((const uint8_t*)trun_raw + hb);
                hte0 = tm & 0xFF; hte1 = (tm >> 8) & 0xFF;
                htu0 = tr & 0xFF; htu1 = (tr >> 8) & 0xFF;
            }
        } else {
#pragma unroll
            for (int p = 0; p < NPASS; p++) {
                const long long b = tileStart + (long long)p * PASS + lane * 4;
                int4 a0 = __ldg((const int4*)((const int*)term_raw + b));
                int4 b0 = __ldg((const int4*)((const int*)trun_raw + b));
                int te[4] = {a0.x, a0.y, a0.z, a0.w};
                int tu[4] = {b0.x, b0.y, b0.z, b0.w};
#pragma unroll
                for (int j = 0; j < 4; j++) {
                    if (te[j]) dmask |= 0x10000u << (p * 4 + j);
                    if (te[j] | tu[j]) dmask |= 1u << (p * 4 + j);
                }
            }
            if (fastHalo) {
                int2 a0 = __ldg((const int2*)((const int*)term_raw + hb));
                int2 b0 = __ldg((const int2*)((const int*)trun_raw + hb));
                hte0 = a0.x; hte1 = a0.y; htu0 = b0.x; htu1 = b0.y;
            }
        }

        float dd[16];
        {
            float nv4[16];
#pragma unroll
            for (int p = 0; p < NPASS; p++) {
                nv4[p*4+0] = NVf[p].x; nv4[p*4+1] = NVf[p].y;
                nv4[p*4+2] = NVf[p].z; nv4[p*4+3] = NVf[p].w;
            }
#pragma unroll
            for (int k = 0; k < 16; k++) {
                float nt = (dmask & (0x10000u << k)) ? 0.f : GAMMA_F;
                dd[k] = fmaf(nt, nv4[k], ddp[k]);
            }
        }

        float iC[5], iD[5];
        {
            float hC = 1.f, hD = 0.f;
            if (fastHalo) {
                float nt0 = hte0 ? 0.f : 1.f, nt1 = hte1 ? 0.f : 1.f;
                float d0 = hR.x + GAMMA_F * nt0 * hN.x - hV.x;
                float d1 = hR.y + GAMMA_F * nt1 * hN.y - hV.y;
                float c0 = (hte0 | htu0) ? 0.f : GL;
                float c1 = (hte1 | htu1) ? 0.f : GL;
                hC = c0 * c1;
                hD = fmaf(c0, d1, d0);
            }
            iC[4] = hC; iD[4] = hD;
        }

#pragma unroll
        for (int p = 0; p < NPASS; p++) {
            const unsigned nib = (dmask >> (p * 4)) & 0xFu;
            float C = (nib == 0u) ? GL4 : 0.f;
            float D = 0.f;
#pragma unroll
            for (int j = 3; j >= 0; j--) {
                float cj = (nib & (1u << j)) ? 0.f : GL;
                D = fmaf(cj, D, dd[p * 4 + j]);
            }
            iC[p] = C; iD[p] = D;
        }

#pragma unroll
        for (int off = 1; off < 32; off <<= 1) {
            float oc[5], od[5];
#pragma unroll
            for (int q = 0; q < 5; q++) {
                oc[q] = __shfl_down_sync(0xFFFFFFFFu, iC[q], off);
                od[q] = __shfl_down_sync(0xFFFFFFFFu, iD[q], off);
            }
            const bool in = (lane + off) < 32;
#pragma unroll
            for (int q = 0; q < 5; q++) {
                float nD = fmaf(iC[q], od[q], iD[q]);
                float nC = iC[q] * oc[q];
                if (in) { iC[q] = nC; iD[q] = nD; }
            }
        }

        float eC[4], eD[4];
#pragma unroll
        for (int q = 0; q < NPASS; q++) {
            eC[q] = __shfl_down_sync(0xFFFFFFFFu, iC[q], 1);
            eD[q] = __shfl_down_sync(0xFFFFFFFFu, iD[q], 1);
            if (lane == 31) { eC[q] = 1.f; eD[q] = 0.f; }
        }

        float aggC[4], aggD[4];
#pragma unroll
        for (int q = 0; q < NPASS; q++) {
            aggC[q] = __shfl_sync(0xFFFFFFFFu, iC[q], 0);
            aggD[q] = __shfl_sync(0xFFFFFFFFu, iD[q], 0);
        }
        const float seedH = __shfl_sync(0xFFFFFFFFu, iD[4], 0);
        float seed[4];
        seed[3] = seedH;
        seed[2] = fmaf(aggC[3], seed[3], aggD[3]);
        seed[1] = fmaf(aggC[2], seed[2], aggD[2]);
        seed[0] = fmaf(aggC[1], seed[1], aggD[1]);

#pragma unroll
        for (int p = 0; p < NPASS; p++) {
            const unsigned nib = (dmask >> (p * 4)) & 0xFu;
            float x = fmaf(eC[p], seed[p], eD[p]);
            float c3 = (nib & 8u) ? 0.f : GL;
            float c2 = (nib & 4u) ? 0.f : GL;
            float c1 = (nib & 2u) ? 0.f : GL;
            float c0 = (nib & 1u) ? 0.f : GL;
            float o0, o1, o2, o3;
            x = fmaf(c3, x, dd[p * 4 + 3]); o3 = x;
            x = fmaf(c2, x, dd[p * 4 + 2]); o2 = x;
            x = fmaf(c1, x, dd[p * 4 + 1]); o1 = x;
            x = fmaf(c0, x, dd[p * 4 + 0]); o0 = x;
            accSum += o0 + o1 + o2 + o3;
            accSq = fmaf(o0, o0, accSq); accSq = fmaf(o1, o1, accSq);
            accSq = fmaf(o2, o2, accSq); accSq = fmaf(o3, o3, accSq);
            *(float4*)(g_adv + tileStart + (long long)p * PASS + lane * 4) =
                make_float4(o0, o1, o2, o3);
        }
    } else {
        // ---------- tail / near-tail tiles (rare) ----------
        const int byteLayout = g_boolByteLayout;
        float seed = 0.f;
        if (tileEnd < (long long)n) {
            float hcc[2], hdd[2];
            const long long hb2 = tileEnd + lane * 2;
#pragma unroll
            for (int j = 0; j < 2; j++) {
                long long idx = hb2 + j;
                hcc[j] = 1.f; hdd[j] = 0.f;
                if (idx < (long long)n) {
                    bool b_te, b_tu;
                    if (byteLayout) {
                        b_te = ((const uint8_t*)term_raw)[idx] != 0;
                        b_tu = ((const uint8_t*)trun_raw)[idx] != 0;
                    } else {
                        b_te = ((const int*)term_raw)[idx] != 0;
                        b_tu = ((const int*)trun_raw)[idx] != 0;
                    }
                    float nt = b_te ? 0.f : 1.f;
                    hdd[j] = rewards[idx] + GAMMA_F * nt * next_values[idx] - values[idx];
                    hcc[j] = (b_te || b_tu) ? 0.f : GL;
                }
            }
            float hC = hcc[0] * hcc[1];
            float hD = fmaf(hcc[0], hdd[1], hdd[0]);
            warp_suffix_scan1(hC, hD, lane);
            seed = __shfl_sync(0xFFFFFFFFu, hD, 0);
        }
        for (int p = NPASS - 1; p >= 0; p--) {
            float cc[4], ddl[4];
            const long long b = tileStart + (long long)p * PASS + lane * 4;
            load_cd4_guard(b, n, byteLayout,
                           rewards, values, next_values, term_raw, trun_raw, cc, ddl);
            float C = 1.f, D = 0.f;
#pragma unroll
            for (int j = 3; j >= 0; j--) { D = fmaf(cc[j], D, ddl[j]); C *= cc[j]; }
            float iCx = C, iDx = D;
            warp_suffix_scan1(iCx, iDx, lane);
            float eCx = __shfl_down_sync(0xFFFFFFFFu, iCx, 1);
            float eDx = __shfl_down_sync(0xFFFFFFFFu, iDx, 1);
            if (lane == 31) { eCx = 1.f; eDx = 0.f; }
            float x = fmaf(eCx, seed, eDx);
#pragma unroll
            for (int j = 3; j >= 0; j--) {
                x = fmaf(cc[j], x, ddl[j]);
                long long idx = b + j;
                if (idx < (long long)n) {
                    g_adv[idx] = x;
                    accSum += x; accSq = fmaf(x, x, accSq);
                }
            }
            float ns = fmaf(iCx, seed, iDx);
            seed = __shfl_sync(0xFFFFFFFFu, ns, 0);
        }
    }

    // ---- warp partial sums -> spread atomic buckets ----
    double ds = (double)accSum, dq = (double)accSq;
#pragma unroll
    for (int o = 16; o > 0; o >>= 1) {
        ds += __shfl_down_sync(0xFFFFFFFFu, ds, o);
        dq += __shfl_down_sync(0xFFFFFFFFu, dq, o);
    }
    bool lastBlock = false;
    if (lane == 0) {
        atomicAdd(&g_psumA[tile & (NBUCKET - 1)], ds);
        atomicAdd(&g_psqA[tile & (NBUCKET - 1)], dq);
        __threadfence();
        unsigned done = atomicAdd(&g_scanDone, 1u);
        lastBlock = (done == (unsigned)(numTiles - 1));
    }
    lastBlock = __shfl_sync(0xFFFFFFFFu, lastBlock ? 1 : 0, 0) != 0;

    // ---- last block: reduce buckets -> mean/rinv ----
    if (lastBlock) {
        __threadfence();
        double ts = 0.0, tq = 0.0;
#pragma unroll
        for (int k = 0; k < NBUCKET / 32; k++) {
            ts += ((volatile double*)g_psumA)[lane + k * 32];
            tq += ((volatile double*)g_psqA)[lane + k * 32];
        }
#pragma unroll
        for (int o = 16; o > 0; o >>= 1) {
            ts += __shfl_down_sync(0xFFFFFFFFu, ts, o);
            tq += __shfl_down_sync(0xFFFFFFFFu, tq, o);
        }
        if (lane == 0) {
            double mean = ts / (double)n;
            double var = (tq - ts * ts / (double)n) / (double)(n - 1);
            if (var < 0.0) var = 0.0;
            g_mean = (float)mean;
            g_rinv = (float)(1.0 / (sqrt(var) + 1e-9));
        }
    }
}

__device__ __forceinline__ void ppo_row(float a, float v, float lp, float olp,
                                        float mean, float rinv, float* o) {
    float an = (a - mean) * rinv;
    float lr = a + v;
    float ratio = __expf(lp - olp);
    float cl = fminf(fmaxf(ratio, 1.f - CLIP_EPS_F), 1.f + CLIP_EPS_F);
    float loss = -fminf(ratio * an, cl * an);
    o[0] = an; o[1] = lr; o[2] = loss;
}

// ===== kernel C: epilogue (round-12 form, verbatim) =====
__global__ __launch_bounds__(OBLOCK)
void output_kernel(const float* __restrict__ values,
                   const float* __restrict__ log_probs,
                   const float* __restrict__ old_log_probs,
                   float* __restrict__ out, int n)
{
    __shared__ float4 s4[3 * OBLOCK];
    const float mean = g_mean, rinv = g_rinv;
    const int t = threadIdx.x;
    const long long blockBase = (long long)blockIdx.x * (OBLOCK * 4);
    const long long b4 = blockBase + t * 4;

    if (blockBase + OBLOCK * 4 <= (long long)n) {
        float4 a   = *(const float4*)(g_adv + b4);
        float4 v   = __ldg((const float4*)(values + b4));
        float4 lp  = __ldg((const float4*)(log_probs + b4));
        float4 olp = __ldg((const float4*)(old_log_probs + b4));
        float o[12];
        ppo_row(a.x, v.x, lp.x, olp.x, mean, rinv, o + 0);
        ppo_row(a.y, v.y, lp.y, olp.y, mean, rinv, o + 3);
        ppo_row(a.z, v.z, lp.z, olp.z, mean, rinv, o + 6);
        ppo_row(a.w, v.w, lp.w, olp.w, mean, rinv, o + 9);
        s4[3 * t + 0] = make_float4(o[0], o[1], o[2],  o[3]);
        s4[3 * t + 1] = make_float4(o[4], o[5], o[6],  o[7]);
        s4[3 * t + 2] = make_float4(o[8], o[9], o[10], o[11]);
        __syncthreads();
        float4* dst = (float4*)(out + blockBase * 3);
        __stcs(dst + t,              s4[t]);
        __stcs(dst + t + OBLOCK,     s4[t + OBLOCK]);
        __stcs(dst + t + 2 * OBLOCK, s4[t + 2 * OBLOCK]);
    } else {
        for (long long i = b4; i < b4 + 4 && i < (long long)n; i++) {
            float o[3];
            ppo_row(g_adv[i], values[i], log_probs[i], old_log_probs[i], mean, rinv, o);
            out[i * 3 + 0] = o[0];
            out[i * 3 + 1] = o[1];
            out[i * 3 + 2] = o[2];
        }
    }
}

extern "C" void kernel_launch(void* const* d_in, const int* in_sizes, int n_in,
                              void* d_out, int out_size) {
    const float* rewards       = (const float*)d_in[0];
    const float* values        = (const float*)d_in[1];
    const float* next_values   = (const float*)d_in[2];
    const float* log_probs     = (const float*)d_in[3];
    const float* old_log_probs = (const float*)d_in[4];
    const void*  terminated    = d_in[5];
    const void*  truncated     = d_in[6];
    float* out = (float*)d_out;

    int n = in_sizes[0];
    int numTiles = (n + TILE - 1) / TILE;              // 4096 for N=2M
    int gridC = (int)(((long long)n + OBLOCK * 4 - 1) / (OBLOCK * 4));   // 2048

    detect_init_kernel<<<1, 256>>>((const uint8_t*)terminated, (const uint8_t*)truncated, n);
    scan_kernel<<<numTiles, WBLOCK>>>(rewards, values, next_values,
                                      terminated, truncated, n, numTiles);
    output_kernel<<<gridC, OBLOCK>>>(values, log_probs, old_log_probs, out, n);
}

// round 16
// speedup vs baseline: 1.3411x; 1.0440x over previous
#include <cuda_runtime.h>
#include <stdint.h>

#define WBLOCK 32                  // scan: 1 warp per block
#define TILE 512                   // elements per tile (one warp)
#define PASS 128                   // elements per pass (4 per lane)
#define NPASS 4
#define NBUCKET 128
#define OBLOCK 256                 // epilogue block

#define GAMMA_F 0.99f
#define LAMBDA_F 0.95f
#define CLIP_EPS_F 0.2f
#define GL (GAMMA_F * LAMBDA_F)
#define GL4 (GL * GL * GL * GL)

// ---- device scratch (zero-init at load; self-cleaning across replays) ----
__device__ float  g_adv[1 << 22];
__device__ double g_psumA[NBUCKET];
__device__ double g_psqA[NBUCKET];
__device__ float  g_mean;
__device__ float  g_rinv;
__device__ unsigned g_scanDone;

// guarded scalar load of 4 (c,d) pairs (tail only)
__device__ __forceinline__ void load_cd4_guard(long long b, int n, int byteLayout,
                                               const float* __restrict__ rewards,
                                               const float* __restrict__ values,
                                               const float* __restrict__ next_values,
                                               const void* __restrict__ term_raw,
                                               const void* __restrict__ trun_raw,
                                               float* cc, float* dd) {
#pragma unroll
    for (int j = 0; j < 4; j++) {
        long long idx = b + j;
        if (idx < (long long)n) {
            bool b_te, b_tu;
            if (byteLayout) {
                b_te = ((const uint8_t*)term_raw)[idx] != 0;
                b_tu = ((const uint8_t*)trun_raw)[idx] != 0;
            } else {
                b_te = ((const int*)term_raw)[idx] != 0;
                b_tu = ((const int*)trun_raw)[idx] != 0;
            }
            float nt = b_te ? 0.f : 1.f;
            dd[j] = rewards[idx] + GAMMA_F * nt * next_values[idx] - values[idx];
            cc[j] = (b_te || b_tu) ? 0.f : GL;
        } else { cc[j] = 1.f; dd[j] = 0.f; }
    }
}

__device__ __forceinline__ void warp_suffix_scan1(float& iC, float& iD, int lane) {
#pragma unroll
    for (int off = 1; off < 32; off <<= 1) {
        float oc = __shfl_down_sync(0xFFFFFFFFu, iC, off);
        float od = __shfl_down_sync(0xFFFFFFFFu, iD, off);
        float nD = fmaf(iC, od, iD);
        float nC = iC * oc;
        if (lane + off < 32) { iC = nC; iD = nD; }
    }
}

// ===== kernel A: scan + in-block detection + last-block stats/cleanup =====
__global__ __launch_bounds__(WBLOCK)
void scan_kernel(const float* __restrict__ rewards,
                 const float* __restrict__ values,
                 const float* __restrict__ next_values,
                 const void* __restrict__ term_raw,
                 const void* __restrict__ trun_raw,
                 int n, int numTiles)
{
    const int lane = threadIdx.x;
    const int tile = blockIdx.x;

    float accSum = 0.f, accSq = 0.f;
    const long long tileStart = (long long)tile * TILE;
    const long long tileEnd   = tileStart + TILE;

    const bool fastHalo = (tileEnd + 64 <= (long long)n);

    // in-block bool-layout detection (first 512B each; L2-broadcast)
    int predv = 0;
    if (n >= 512) {
        uint4 dx = __ldg((const uint4*)term_raw + lane);
        uint4 dy = __ldg((const uint4*)trun_raw + lane);
        predv = ((dx.x | dx.y | dx.z | dx.w | dy.x | dy.y | dy.z | dy.w) & 0xFFFFFF00u) != 0;
    } else {
        for (int i = lane; i < n; i += 32)
            if ((i & 3) && (((const uint8_t*)term_raw)[i] | ((const uint8_t*)trun_raw)[i]))
                predv = 1;
    }

    if (tileEnd <= (long long)n && (fastHalo || tileEnd == (long long)n)) {
        // ---------- fast path ----------
        // 1) float loads: unconditional, issue immediately
        float ddp[16];           // r - v
        float4 NVf[NPASS];
#pragma unroll
        for (int p = 0; p < NPASS; p++) {
            const long long b = tileStart + (long long)p * PASS + lane * 4;
            float4 rr = __ldg((const float4*)(rewards + b));
            float4 vv = __ldg((const float4*)(values + b));
            NVf[p]    = __ldg((const float4*)(next_values + b));
            ddp[p*4+0] = rr.x - vv.x;
            ddp[p*4+1] = rr.y - vv.y;
            ddp[p*4+2] = rr.z - vv.z;
            ddp[p*4+3] = rr.w - vv.w;
        }
        float2 hR = make_float2(0.f, 0.f), hV = hR, hN = hR;
        const long long hb = tileEnd + lane * 2;
        if (fastHalo) {
            hR = __ldg((const float2*)(rewards + hb));
            hV = __ldg((const float2*)(values + hb));
            hN = __ldg((const float2*)(next_values + hb));
        }

        // 2) resolve layout, then bool loads
        const int byteLayout = __any_sync(0xFFFFFFFFu, predv);
        unsigned dmask = 0;
        int hte0 = 0, hte1 = 0, htu0 = 0, htu1 = 0;
        if (byteLayout) {
#pragma unroll
            for (int p = 0; p < NPASS; p++) {
                const long long b = tileStart + (long long)p * PASS + lane * 4;
                unsigned tm = *(const unsigned*)((const uint8_t*)term_raw + b);
                unsigned tr = *(const unsigned*)((const uint8_t*)trun_raw + b);
#pragma unroll
                for (int j = 0; j < 4; j++) {
                    int te = (int)((tm >> (8 * j)) & 0xFFu);
                    int tu = (int)((tr >> (8 * j)) & 0xFFu);
                    if (te) dmask |= 0x10000u << (p * 4 + j);
                    if (te | tu) dmask |= 1u << (p * 4 + j);
                }
            }
            if (fastHalo) {
                unsigned short tm = *(const unsigned short*)((const uint8_t*)term_raw + hb);
                unsigned short tr = *(const unsigned short*)((const uint8_t*)trun_raw + hb);
                hte0 = tm & 0xFF; hte1 = (tm >> 8) & 0xFF;
                htu0 = tr & 0xFF; htu1 = (tr >> 8) & 0xFF;
            }
        } else {
#pragma unroll
            for (int p = 0; p < NPASS; p++) {
                const long long b = tileStart + (long long)p * PASS + lane * 4;
                int4 a0 = __ldg((const int4*)((const int*)term_raw + b));
                int4 b0 = __ldg((const int4*)((const int*)trun_raw + b));
                int te[4] = {a0.x, a0.y, a0.z, a0.w};
                int tu[4] = {b0.x, b0.y, b0.z, b0.w};
#pragma unroll
                for (int j = 0; j < 4; j++) {
                    if (te[j]) dmask |= 0x10000u << (p * 4 + j);
                    if (te[j] | tu[j]) dmask |= 1u << (p * 4 + j);
                }
            }
            if (fastHalo) {
                int2 a0 = __ldg((const int2*)((const int*)term_raw + hb));
                int2 b0 = __ldg((const int2*)((const int*)trun_raw + hb));
                hte0 = a0.x; hte1 = a0.y; htu0 = b0.x; htu1 = b0.y;
            }
        }

        // 3) fold deltas
        float dd[16];
        {
            float nv4[16];
#pragma unroll
            for (int p = 0; p < NPASS; p++) {
                nv4[p*4+0] = NVf[p].x; nv4[p*4+1] = NVf[p].y;
                nv4[p*4+2] = NVf[p].z; nv4[p*4+3] = NVf[p].w;
            }
#pragma unroll
            for (int k = 0; k < 16; k++) {
                float nt = (dmask & (0x10000u << k)) ? 0.f : GAMMA_F;
                dd[k] = fmaf(nt, nv4[k], ddp[k]);
            }
        }

        float iC[5], iD[5];
        {
            float hC = 1.f, hD = 0.f;
            if (fastHalo) {
                float nt0 = hte0 ? 0.f : 1.f, nt1 = hte1 ? 0.f : 1.f;
                float d0 = hR.x + GAMMA_F * nt0 * hN.x - hV.x;
                float d1 = hR.y + GAMMA_F * nt1 * hN.y - hV.y;
                float c0 = (hte0 | htu0) ? 0.f : GL;
                float c1 = (hte1 | htu1) ? 0.f : GL;
                hC = c0 * c1;
                hD = fmaf(c0, d1, d0);
            }
            iC[4] = hC; iD[4] = hD;
        }

#pragma unroll
        for (int p = 0; p < NPASS; p++) {
            const unsigned nib = (dmask >> (p * 4)) & 0xFu;
            float C = (nib == 0u) ? GL4 : 0.f;
            float D = 0.f;
#pragma unroll
            for (int j = 3; j >= 0; j--) {
                float cj = (nib & (1u << j)) ? 0.f : GL;
                D = fmaf(cj, D, dd[p * 4 + j]);
            }
            iC[p] = C; iD[p] = D;
        }

        // 5 interleaved suffix scans
#pragma unroll
        for (int off = 1; off < 32; off <<= 1) {
            float oc[5], od[5];
#pragma unroll
            for (int q = 0; q < 5; q++) {
                oc[q] = __shfl_down_sync(0xFFFFFFFFu, iC[q], off);
                od[q] = __shfl_down_sync(0xFFFFFFFFu, iD[q], off);
            }
            const bool in = (lane + off) < 32;
#pragma unroll
            for (int q = 0; q < 5; q++) {
                float nD = fmaf(iC[q], od[q], iD[q]);
                float nC = iC[q] * oc[q];
                if (in) { iC[q] = nC; iD[q] = nD; }
            }
        }

        float eC[4], eD[4];
#pragma unroll
        for (int q = 0; q < NPASS; q++) {
            eC[q] = __shfl_down_sync(0xFFFFFFFFu, iC[q], 1);
            eD[q] = __shfl_down_sync(0xFFFFFFFFu, iD[q], 1);
            if (lane == 31) { eC[q] = 1.f; eD[q] = 0.f; }
        }

        float aggC[4], aggD[4];
#pragma unroll
        for (int q = 0; q < NPASS; q++) {
            aggC[q] = __shfl_sync(0xFFFFFFFFu, iC[q], 0);
            aggD[q] = __shfl_sync(0xFFFFFFFFu, iD[q], 0);
        }
        const float seedH = __shfl_sync(0xFFFFFFFFu, iD[4], 0);
        float seed[4];
        seed[3] = seedH;
        seed[2] = fmaf(aggC[3], seed[3], aggD[3]);
        seed[1] = fmaf(aggC[2], seed[2], aggD[2]);
        seed[0] = fmaf(aggC[1], seed[1], aggD[1]);

#pragma unroll
        for (int p = 0; p < NPASS; p++) {
            const unsigned nib = (dmask >> (p * 4)) & 0xFu;
            float x = fmaf(eC[p], seed[p], eD[p]);
            float c3 = (nib & 8u) ? 0.f : GL;
            float c2 = (nib & 4u) ? 0.f : GL;
            float c1 = (nib & 2u) ? 0.f : GL;
            float c0 = (nib & 1u) ? 0.f : GL;
            float o0, o1, o2, o3;
            x = fmaf(c3, x, dd[p * 4 + 3]); o3 = x;
            x = fmaf(c2, x, dd[p * 4 + 2]); o2 = x;
            x = fmaf(c1, x, dd[p * 4 + 1]); o1 = x;
            x = fmaf(c0, x, dd[p * 4 + 0]); o0 = x;
            accSum += o0 + o1 + o2 + o3;
            accSq = fmaf(o0, o0, accSq); accSq = fmaf(o1, o1, accSq);
            accSq = fmaf(o2, o2, accSq); accSq = fmaf(o3, o3, accSq);
            *(float4*)(g_adv + tileStart + (long long)p * PASS + lane * 4) =
                make_float4(o0, o1, o2, o3);
        }
    } else {
        // ---------- tail / near-tail tiles (rare) ----------
        const int byteLayout = __any_sync(0xFFFFFFFFu, predv);
        float seed = 0.f;
        if (tileEnd < (long long)n) {
            float hcc[2], hdd[2];
            const long long hb2 = tileEnd + lane * 2;
#pragma unroll
            for (int j = 0; j < 2; j++) {
                long long idx = hb2 + j;
                hcc[j] = 1.f; hdd[j] = 0.f;
                if (idx < (long long)n) {
                    bool b_te, b_tu;
                    if (byteLayout) {
                        b_te = ((const uint8_t*)term_raw)[idx] != 0;
                        b_tu = ((const uint8_t*)trun_raw)[idx] != 0;
                    } else {
                        b_te = ((const int*)term_raw)[idx] != 0;
                        b_tu = ((const int*)trun_raw)[idx] != 0;
                    }
                    float nt = b_te ? 0.f : 1.f;
                    hdd[j] = rewards[idx] + GAMMA_F * nt * next_values[idx] - values[idx];
                    hcc[j] = (b_te || b_tu) ? 0.f : GL;
                }
            }
            float hC = hcc[0] * hcc[1];
            float hD = fmaf(hcc[0], hdd[1], hdd[0]);
            warp_suffix_scan1(hC, hD, lane);
            seed = __shfl_sync(0xFFFFFFFFu, hD, 0);
        }
        for (int p = NPASS - 1; p >= 0; p--) {
            float cc[4], ddl[4];
            const long long b = tileStart + (long long)p * PASS + lane * 4;
            load_cd4_guard(b, n, byteLayout,
                           rewards, values, next_values, term_raw, trun_raw, cc, ddl);
            float C = 1.f, D = 0.f;
#pragma unroll
            for (int j = 3; j >= 0; j--) { D = fmaf(cc[j], D, ddl[j]); C *= cc[j]; }
            float iCx = C, iDx = D;
            warp_suffix_scan1(iCx, iDx, lane);
            float eCx = __shfl_down_sync(0xFFFFFFFFu, iCx, 1);
            float eDx = __shfl_down_sync(0xFFFFFFFFu, iDx, 1);
            if (lane == 31) { eCx = 1.f; eDx = 0.f; }
            float x = fmaf(eCx, seed, eDx);
#pragma unroll
            for (int j = 3; j >= 0; j--) {
                x = fmaf(cc[j], x, ddl[j]);
                long long idx = b + j;
                if (idx < (long long)n) {
                    g_adv[idx] = x;
                    accSum += x; accSq = fmaf(x, x, accSq);
                }
            }
            float ns = fmaf(iCx, seed, iDx);
            seed = __shfl_sync(0xFFFFFFFFu, ns, 0);
        }
    }

    // ---- warp partial sums -> spread atomic buckets ----
    double ds = (double)accSum, dq = (double)accSq;
#pragma unroll
    for (int o = 16; o > 0; o >>= 1) {
        ds += __shfl_down_sync(0xFFFFFFFFu, ds, o);
        dq += __shfl_down_sync(0xFFFFFFFFu, dq, o);
    }
    bool lastBlock = false;
    if (lane == 0) {
        atomicAdd(&g_psumA[tile & (NBUCKET - 1)], ds);
        atomicAdd(&g_psqA[tile & (NBUCKET - 1)], dq);
        __threadfence();
        unsigned done = atomicAdd(&g_scanDone, 1u);
        lastBlock = (done == (unsigned)(numTiles - 1));
    }
    lastBlock = __shfl_sync(0xFFFFFFFFu, lastBlock ? 1 : 0, 0) != 0;

    // ---- last block: reduce buckets -> mean/rinv, then self-clean ----
    if (lastBlock) {
        __threadfence();
        double ts = 0.0, tq = 0.0;
#pragma unroll
        for (int k = 0; k < NBUCKET / 32; k++) {
            ts += ((volatile double*)g_psumA)[lane + k * 32];
            tq += ((volatile double*)g_psqA)[lane + k * 32];
        }
#pragma unroll
        for (int o = 16; o > 0; o >>= 1) {
            ts += __shfl_down_sync(0xFFFFFFFFu, ts, o);
            tq += __shfl_down_sync(0xFFFFFFFFu, tq, o);
        }
        if (lane == 0) {
            double mean = ts / (double)n;
            double var = (tq - ts * ts / (double)n) / (double)(n - 1);
            if (var < 0.0) var = 0.0;
            g_mean = (float)mean;
            g_rinv = (float)(1.0 / (sqrt(var) + 1e-9));
        }
        __syncwarp();
        // self-clean for next graph replay (reads above are complete)
#pragma unroll
        for (int k = 0; k < NBUCKET / 32; k++) {
            g_psumA[lane + k * 32] = 0.0;
            g_psqA[lane + k * 32]  = 0.0;
        }
        if (lane == 0) {
            __threadfence();
            g_scanDone = 0;
        }
    }
}

__device__ __forceinline__ void ppo_row(float a, float v, float lp, float olp,
                                        float mean, float rinv, float* o) {
    float an = (a - mean) * rinv;
    float lr = a + v;
    float ratio = __expf(lp - olp);
    float cl = fminf(fmaxf(ratio, 1.f - CLIP_EPS_F), 1.f + CLIP_EPS_F);
    float loss = -fminf(ratio * an, cl * an);
    o[0] = an; o[1] = lr; o[2] = loss;
}

// ===== kernel C: epilogue (round-12 form, verbatim) =====
__global__ __launch_bounds__(OBLOCK)
void output_kernel(const float* __restrict__ values,
                   const float* __restrict__ log_probs,
                   const float* __restrict__ old_log_probs,
                   float* __restrict__ out, int n)
{
    __shared__ float4 s4[3 * OBLOCK];
    const float mean = g_mean, rinv = g_rinv;
    const int t = threadIdx.x;
    const long long blockBase = (long long)blockIdx.x * (OBLOCK * 4);
    const long long b4 = blockBase + t * 4;

    if (blockBase + OBLOCK * 4 <= (long long)n) {
        float4 a   = *(const float4*)(g_adv + b4);
        float4 v   = __ldg((const float4*)(values + b4));
        float4 lp  = __ldg((const float4*)(log_probs + b4));
        float4 olp = __ldg((const float4*)(old_log_probs + b4));
        float o[12];
        ppo_row(a.x, v.x, lp.x, olp.x, mean, rinv, o + 0);
        ppo_row(a.y, v.y, lp.y, olp.y, mean, rinv, o + 3);
        ppo_row(a.z, v.z, lp.z, olp.z, mean, rinv, o + 6);
        ppo_row(a.w, v.w, lp.w, olp.w, mean, rinv, o + 9);
        s4[3 * t + 0] = make_float4(o[0], o[1], o[2],  o[3]);
        s4[3 * t + 1] = make_float4(o[4], o[5], o[6],  o[7]);
        s4[3 * t + 2] = make_float4(o[8], o[9], o[10], o[11]);
        __syncthreads();
        float4* dst = (float4*)(out + blockBase * 3);
        __stcs(dst + t,              s4[t]);
        __stcs(dst + t + OBLOCK,     s4[t + OBLOCK]);
        __stcs(dst + t + 2 * OBLOCK, s4[t + 2 * OBLOCK]);
    } else {
        for (long long i = b4; i < b4 + 4 && i < (long long)n; i++) {
            float o[3];
            ppo_row(g_adv[i], values[i], log_probs[i], old_log_probs[i], mean, rinv, o);
            out[i * 3 + 0] = o[0];
            out[i * 3 + 1] = o[1];
            out[i * 3 + 2] = o[2];
        }
    }
}

extern "C" void kernel_launch(void* const* d_in, const int* in_sizes, int n_in,
                              void* d_out, int out_size) {
    const float* rewards       = (const float*)d_in[0];
    const float* values        = (const float*)d_in[1];
    const float* next_values   = (const float*)d_in[2];
    const float* log_probs     = (const float*)d_in[3];
    const float* old_log_probs = (const float*)d_in[4];
    const void*  terminated    = d_in[5];
    const void*  truncated     = d_in[6];
    float* out = (float*)d_out;

    int n = in_sizes[0];
    int numTiles = (n + TILE - 1) / TILE;              // 4096 for N=2M
    int gridC = (int)(((long long)n + OBLOCK * 4 - 1) / (OBLOCK * 4));   // 2048

    scan_kernel<<<numTiles, WBLOCK>>>(rewards, values, next_values,
                                      terminated, truncated, n, numTiles);
    output_kernel<<<gridC, OBLOCK>>>(values, log_probs, old_log_probs, out, n);
}